// round 12
// baseline (speedup 1.0000x reference)
#include <cuda_runtime.h>
#include <cstdint>

// ---------------- problem constants ----------------
#define BB      256
#define DD      256
#define NCOLS   131072
#define NHALF   65536
#define TN      128
#define NTILES  (NCOLS / TN)    // 1024
#define NGRID   148
#define TEMP_INV 20.0f
#define SHIFT    20.0f
#define RR       0.2f
#define QS       254.0f                       // int8 scale (clip +-0.5)
#define DQ       (TEMP_INV / (QS * QS))       // s32 dot -> logit

// smem: acc[512] @0 (2048B), A @2048 (256x256B=65536), B @67584 (3x8192B)
#define SM_A      2048u
#define SM_B      (SM_A + 65536u)
#define SM_TOTAL  (SM_B + 3u * 8192u)   // 92160

__device__ float g_sums[2 * BB];
__device__ float g_tgt[2 * BB];

// ---------------- helpers ----------------
__device__ __forceinline__ uint32_t smem_u32(const void* p) {
    uint32_t a;
    asm("{ .reg .u64 t; cvta.to.shared.u64 t, %1; cvt.u32.u64 %0, t; }" : "=r"(a) : "l"(p));
    return a;
}
__device__ __forceinline__ uint32_t q8x4(float4 f) {
    int a = __float2int_rn(f.x * QS), b = __float2int_rn(f.y * QS),
        c = __float2int_rn(f.z * QS), d = __float2int_rn(f.w * QS);
    a = max(-127, min(127, a)); b = max(-127, min(127, b));
    c = max(-127, min(127, c)); d = max(-127, min(127, d));
    return (a & 0xff) | ((b & 0xff) << 8) | ((c & 0xff) << 16) | ((d & 0xff) << 24);
}

#define LDSM_X4(r, a) asm volatile( \
    "ldmatrix.sync.aligned.m8n8.x4.shared.b16 {%0,%1,%2,%3}, [%4];" \
    : "=r"((r)[0]), "=r"((r)[1]), "=r"((r)[2]), "=r"((r)[3]) : "r"(a))
#define LDSM_X2(r, a) asm volatile( \
    "ldmatrix.sync.aligned.m8n8.x2.shared.b16 {%0,%1}, [%2];" \
    : "=r"((r)[0]), "=r"((r)[1]) : "r"(a))
#define MMAS8(d, a, b) asm volatile( \
    "mma.sync.aligned.m16n8k32.row.col.s32.s8.s8.s32 " \
    "{%0,%1,%2,%3}, {%4,%5,%6,%7}, {%8,%9}, {%0,%1,%2,%3};" \
    : "+r"((d)[0]), "+r"((d)[1]), "+r"((d)[2]), "+r"((d)[3]) \
    : "r"((a)[0]), "r"((a)[1]), "r"((a)[2]), "r"((a)[3]), "r"((b)[0]), "r"((b)[1]))

// B chunk staging: thread t covers feature row col0 + (t>>2), k-quarter (t&3)
__device__ __forceinline__ void loadB(const float* __restrict__ feat, size_t col0,
                                      int kc, int t, float4 f4[4]) {
    const float4* s = (const float4*)(feat + (col0 + (size_t)(t >> 2)) * DD
                                      + kc * 64 + (t & 3) * 16);
    f4[0] = s[0]; f4[1] = s[1]; f4[2] = s[2]; f4[3] = s[3];
}
__device__ __forceinline__ void storeB(char* Bsm, int slot, int t, const float4 f4[4]) {
    const int n = t >> 2, seg = t & 3;
    uint4 pk = { q8x4(f4[0]), q8x4(f4[1]), q8x4(f4[2]), q8x4(f4[3]) };
    *(uint4*)(Bsm + slot * 8192 + n * 64 + ((seg ^ ((n >> 1) & 3)) * 16)) = pk;
}

// ---------------- persistent fused GEMM (int8 IMMA) + exp row-sum ----------------
__global__ void __launch_bounds__(512, 1) main_kernel(const float* __restrict__ inp,
                                                      const float* __restrict__ feat) {
    extern __shared__ __align__(1024) char smem[];
    float* acc = (float*)smem;                 // [2][256] persistent row sums
    char* Asm = smem + SM_A;
    char* Bsm = smem + SM_B;
    const uint32_t Abase = smem_u32(Asm), Bbase = smem_u32(Bsm);

    const int t = threadIdx.x, lane = t & 31, wid = t >> 5;
    const int wm = wid & 3, wn = wid >> 2;
    const int bid = blockIdx.x;

    if (t < 512) acc[t] = 0.0f;

    // ---- prologue: convert+cache A (256x256 f32 -> s8, swizzled 256B rows) ----
#pragma unroll
    for (int i = 0; i < 8; i++) {
        int g = t + i * 512;                   // 16B chunk id 0..4095
        int row = g >> 4, c = g & 15;
        const float4* s = (const float4*)(inp + row * DD + c * 16);
        uint4 pk = { q8x4(s[0]), q8x4(s[1]), q8x4(s[2]), q8x4(s[3]) };
        *(uint4*)(Asm + row * 256 + ((c ^ (row & 7)) * 16)) = pk;
    }

    const int nt_cta = (NTILES - bid + NGRID - 1) / NGRID;
    const int total = nt_cta * 4;              // k64 chunks

    int d[4][4][4];
#pragma unroll
    for (int mt = 0; mt < 4; mt++)
#pragma unroll
        for (int nt = 0; nt < 4; nt++)
#pragma unroll
            for (int q = 0; q < 4; q++) d[mt][nt][q] = 0;

    float4 f4[4];
    loadB(feat, (size_t)bid * TN, 0, t, f4);
    __syncthreads();                            // A published

    for (int s = 0; s <= total; s++) {
        if (s < total) storeB(Bsm, s % 3, t, f4);
        if (s + 1 < total) {
            int c = s + 1;
            size_t col0 = (size_t)(bid + (c >> 2) * NGRID) * TN;
            loadB(feat, col0, c & 3, t, f4);
        }
        __syncthreads();

        if (s >= 1) {
            const int c = s - 1;
            const uint32_t Bslot = Bbase + (uint32_t)(c % 3) * 8192u;
            const int kc = c & 3;
#pragma unroll
            for (int ks = 0; ks < 2; ks++) {   // k32 steps
                const int gks = kc * 2 + ks;   // 0..7
                uint32_t a[4][4];
#pragma unroll
                for (int mt = 0; mt < 4; mt++) {
                    int r = wm * 64 + mt * 16 + (lane & 15);
                    uint32_t addr = Abase + r * 256
                                  + (((2 * gks + (lane >> 4)) ^ (r & 7)) * 16);
                    LDSM_X4(a[mt], addr);
                }
                uint32_t b[4][2];
#pragma unroll
                for (int nt = 0; nt < 4; nt++) {
                    int n = wn * 32 + nt * 8 + (lane & 7);
                    uint32_t addr = Bslot + n * 64
                                  + (((2 * ks + ((lane >> 3) & 1)) ^ ((n >> 1) & 3)) * 16);
                    LDSM_X2(b[nt], addr);
                }
#pragma unroll
                for (int mt = 0; mt < 4; mt++)
#pragma unroll
                    for (int nt = 0; nt < 4; nt++)
                        MMAS8(d[mt][nt], a[mt], b[nt]);
            }

            if (kc == 3) {                      // tile finished: fused epilogue
                const int tile = bid + (c >> 2) * NGRID;
                float* ah = acc + ((tile >= NTILES / 2) ? 256 : 0);
#pragma unroll
                for (int mt = 0; mt < 4; mt++) {
                    float slo = 0.0f, shi = 0.0f;
#pragma unroll
                    for (int nt = 0; nt < 4; nt++) {
                        slo += __expf(fmaf((float)d[mt][nt][0], DQ, -SHIFT))
                             + __expf(fmaf((float)d[mt][nt][1], DQ, -SHIFT));
                        shi += __expf(fmaf((float)d[mt][nt][2], DQ, -SHIFT))
                             + __expf(fmaf((float)d[mt][nt][3], DQ, -SHIFT));
#pragma unroll
                        for (int q = 0; q < 4; q++) d[mt][nt][q] = 0;
                    }
#pragma unroll
                    for (int o = 1; o <= 2; o <<= 1) {
                        slo += __shfl_xor_sync(0xffffffffu, slo, o);
                        shi += __shfl_xor_sync(0xffffffffu, shi, o);
                    }
                    if ((lane & 3) == 0) {
                        int r = wm * 64 + mt * 16 + (lane >> 2);
                        atomicAdd(&ah[r], slo);
                        atomicAdd(&ah[r + 8], shi);
                    }
                }
            }
        }
    }

    __syncthreads();
    atomicAdd(&g_sums[t], acc[t]);
}

// ---------------- targets (fp32 exact) + g_sums init; 8 warps/block ----------------
__global__ void __launch_bounds__(256) tgt_kernel(const float* __restrict__ inp,
                                                  const float* __restrict__ feat,
                                                  const void* __restrict__ targets) {
    const int lane = threadIdx.x & 31, w = threadIdx.x >> 5;
    const int pair = blockIdx.x * 8 + w;
    const int b = pair >> 1, h = pair & 1;

    if (blockIdx.x == 0) {
        g_sums[threadIdx.x] = 0.0f;
        g_sums[256 + threadIdx.x] = 0.0f;
    }

    const int* p32 = (const int*)targets;
    unsigned odd_nz = __ballot_sync(0xffffffffu, p32[2 * lane + 1] != 0);
    const bool is64 = (odd_nz == 0u);
    long long tb = is64 ? ((const long long*)targets)[b] : (long long)p32[b];

    const float4* fa = (const float4*)(feat + (tb + (long long)h * NHALF) * DD);
    const float4* ia = (const float4*)(inp + (size_t)b * DD);
    float s = 0.0f;
#pragma unroll
    for (int j = 0; j < 2; j++) {
        float4 x = ia[lane + j * 32], y = fa[lane + j * 32];
        s = fmaf(x.x, y.x, s); s = fmaf(x.y, y.y, s);
        s = fmaf(x.z, y.z, s); s = fmaf(x.w, y.w, s);
    }
#pragma unroll
    for (int o = 16; o > 0; o >>= 1) s += __shfl_xor_sync(0xffffffffu, s, o);
    if (lane == 0) g_tgt[h * BB + b] = s * TEMP_INV;
}

// ---------------- fold to scalar ----------------
__global__ void final_kernel(float* __restrict__ out) {
    const int t = threadIdx.x;
    float dm = (logf(g_sums[t]) + SHIFT) - g_tgt[t];
    float dh = (logf(g_sums[BB + t]) + SHIFT) - g_tgt[BB + t];
    __shared__ float smm[8], smh[8];
#pragma unroll
    for (int o = 16; o > 0; o >>= 1) {
        dm += __shfl_xor_sync(0xffffffffu, dm, o);
        dh += __shfl_xor_sync(0xffffffffu, dh, o);
    }
    if ((t & 31) == 0) { smm[t >> 5] = dm; smh[t >> 5] = dh; }
    __syncthreads();
    if (t == 0) {
        float sm = 0.0f, sh = 0.0f;
#pragma unroll
        for (int i = 0; i < 8; i++) { sm += smm[i]; sh += smh[i]; }
        out[0] = 0.5f * (sh * (1.0f / BB) + fmaxf(sm * (1.0f / BB) - RR, 0.0f));
    }
}

extern "C" void kernel_launch(void* const* d_in, const int* in_sizes, int n_in,
                              void* d_out, int out_size) {
    const float* inp     = (const float*)d_in[0];
    const void*  targets = d_in[1];
    const float* feat    = (const float*)d_in[2];
    float* out = (float*)d_out;

    cudaFuncSetAttribute(main_kernel, cudaFuncAttributeMaxDynamicSharedMemorySize, SM_TOTAL);

    tgt_kernel<<<64, 256>>>(inp, feat, targets);
    main_kernel<<<NGRID, 512, SM_TOTAL>>>(inp, feat);
    final_kernel<<<1, 256>>>(out);
}

// round 13
// speedup vs baseline: 2.1964x; 2.1964x over previous
#include <cuda_runtime.h>
#include <cuda_bf16.h>
#include <cstdint>

// ---------------- problem constants ----------------
#define BB      256
#define DD      256
#define NCOLS   131072
#define NHALF   65536
#define TN      128
#define NTILES  (NCOLS / TN)    // 1024
#define NGRID   148
#define TGT_CTA0 136            // CTAs 136..147 have 6 tiles (others 7) -> do targets
#define TEMP_INV 20.0f
#define SHIFT    20.0f
#define RR       0.2f

// smem: acc[512] @0 (2048B), A @2048 (256x512B=131072B), B @133120 (3x16384B)
#define SM_A      2048u
#define SM_B      (SM_A + 131072u)
#define SM_TOTAL  (SM_B + 3u * 16384u)   // 182272

__device__ float g_sums[2 * BB];   // zeroed at end of every run (static-init 0)
__device__ float g_tgt[2 * BB];
__device__ int   g_done;           // completion counter, reset every run

// ---------------- helpers ----------------
__device__ __forceinline__ uint32_t smem_u32(const void* p) {
    uint32_t a;
    asm("{ .reg .u64 t; cvta.to.shared.u64 t, %1; cvt.u32.u64 %0, t; }" : "=r"(a) : "l"(p));
    return a;
}
#define CVT_BF2(res, a, b) asm("cvt.rn.satfinite.bf16x2.f32 %0, %1, %2;" : "=r"(res) : "f"(b), "f"(a))

#define LDSM_X4(r, a) asm volatile( \
    "ldmatrix.sync.aligned.m8n8.x4.shared.b16 {%0,%1,%2,%3}, [%4];" \
    : "=r"((r)[0]), "=r"((r)[1]), "=r"((r)[2]), "=r"((r)[3]) : "r"(a))
#define LDSM_X2(r, a) asm volatile( \
    "ldmatrix.sync.aligned.m8n8.x2.shared.b16 {%0,%1}, [%2];" \
    : "=r"((r)[0]), "=r"((r)[1]) : "r"(a))
#define MMA16816(d, a, b) asm volatile( \
    "mma.sync.aligned.m16n8k16.row.col.f32.bf16.bf16.f32 " \
    "{%0,%1,%2,%3}, {%4,%5,%6,%7}, {%8,%9}, {%0,%1,%2,%3};" \
    : "+f"((d)[0]), "+f"((d)[1]), "+f"((d)[2]), "+f"((d)[3]) \
    : "r"((a)[0]), "r"((a)[1]), "r"((a)[2]), "r"((a)[3]), "r"((b)[0]), "r"((b)[1]))

// B chunk staging: thread t covers feature row col0 + (t>>2), k-quarter (t&3)
__device__ __forceinline__ void loadB(const float* __restrict__ feat, size_t col0,
                                      int kc, int t, float4 f4[4]) {
    const float4* s = (const float4*)(feat + (col0 + (size_t)(t >> 2)) * DD
                                      + kc * 64 + (t & 3) * 16);
    f4[0] = s[0]; f4[1] = s[1]; f4[2] = s[2]; f4[3] = s[3];
}
__device__ __forceinline__ void storeB(char* Bsm, int slot, int t, const float4 f4[4]) {
    const int n = t >> 2, seg = t & 3;
    uint4 p0, p1;
    CVT_BF2(p0.x, f4[0].x, f4[0].y); CVT_BF2(p0.y, f4[0].z, f4[0].w);
    CVT_BF2(p0.z, f4[1].x, f4[1].y); CVT_BF2(p0.w, f4[1].z, f4[1].w);
    CVT_BF2(p1.x, f4[2].x, f4[2].y); CVT_BF2(p1.y, f4[2].z, f4[2].w);
    CVT_BF2(p1.z, f4[3].x, f4[3].y); CVT_BF2(p1.w, f4[3].z, f4[3].w);
    char* base = Bsm + slot * 16384 + n * 128;
    *(uint4*)(base + (((seg * 2)     ^ (n & 7)) * 16)) = p0;
    *(uint4*)(base + (((seg * 2 + 1) ^ (n & 7)) * 16)) = p1;
}

// ---------------- single fused kernel ----------------
__global__ void __launch_bounds__(512, 1) main_kernel(const float* __restrict__ inp,
                                                      const float* __restrict__ feat,
                                                      const void* __restrict__ targets,
                                                      float* __restrict__ out) {
    extern __shared__ __align__(1024) char smem[];
    float* acc = (float*)smem;                 // [2][256] persistent row sums
    char* Asm = smem + SM_A;
    char* Bsm = smem + SM_B;
    const uint32_t Abase = smem_u32(Asm), Bbase = smem_u32(Bsm);

    const int t = threadIdx.x, lane = t & 31, wid = t >> 5;
    const int wm = wid & 3, wn = wid >> 2;
    const int bid = blockIdx.x;

    if (t < 512) acc[t] = 0.0f;

    // ---- prologue: convert+cache A (256x256 f32 -> bf16, swizzled) ----
#pragma unroll
    for (int i = 0; i < 16; i++) {
        int g = t + i * 512;                   // 16B bf16 chunk id 0..8191
        int row = g >> 5, c = g & 31;
        const float4* s = (const float4*)(inp + row * DD + c * 8);
        float4 a = s[0], b = s[1];
        uint4 pk;
        CVT_BF2(pk.x, a.x, a.y); CVT_BF2(pk.y, a.z, a.w);
        CVT_BF2(pk.z, b.x, b.y); CVT_BF2(pk.w, b.z, b.w);
        *(uint4*)(Asm + row * 512 + ((c ^ (row & 7)) * 16)) = pk;
    }

    // ---- fused target dots (light CTAs only): fp32 exact ----
    if (bid >= TGT_CTA0) {
        const int* p32 = (const int*)targets;
        unsigned odd_nz = __ballot_sync(0xffffffffu, p32[2 * lane + 1] != 0);
        const bool is64 = (odd_nz == 0u);
        for (int p = wid + (bid - TGT_CTA0) * 16; p < 512; p += (NGRID - TGT_CTA0) * 16) {
            const int b = p >> 1, h = p & 1;
            long long tb = is64 ? ((const long long*)targets)[b] : (long long)p32[b];
            const float4* fa = (const float4*)(feat + (tb + (long long)h * NHALF) * DD);
            const float4* ia = (const float4*)(inp + (size_t)b * DD);
            float s = 0.0f;
#pragma unroll
            for (int j = 0; j < 2; j++) {
                float4 x = ia[lane + j * 32], y = fa[lane + j * 32];
                s = fmaf(x.x, y.x, s); s = fmaf(x.y, y.y, s);
                s = fmaf(x.z, y.z, s); s = fmaf(x.w, y.w, s);
            }
#pragma unroll
            for (int o = 16; o > 0; o >>= 1) s += __shfl_xor_sync(0xffffffffu, s, o);
            if (lane == 0) g_tgt[h * BB + b] = s * TEMP_INV;
        }
    }

    const int nt_cta = (NTILES - bid + NGRID - 1) / NGRID;
    const int total = nt_cta * 4;              // k64 chunks

    float d[4][4][4];
#pragma unroll
    for (int mt = 0; mt < 4; mt++)
#pragma unroll
        for (int nt = 0; nt < 4; nt++)
#pragma unroll
            for (int q = 0; q < 4; q++) d[mt][nt][q] = 0.0f;

    float4 f4[4];
    loadB(feat, (size_t)bid * TN, 0, t, f4);
    __syncthreads();                            // A published

    for (int s = 0; s <= total; s++) {
        if (s < total) storeB(Bsm, s % 3, t, f4);
        if (s + 1 < total) {
            int c = s + 1;
            size_t col0 = (size_t)(bid + (c >> 2) * NGRID) * TN;
            loadB(feat, col0, c & 3, t, f4);
        }
        __syncthreads();

        if (s >= 1) {
            const int c = s - 1;
            const uint32_t Bslot = Bbase + (uint32_t)(c % 3) * 16384u;
            const int kc = c & 3;
#pragma unroll
            for (int ks = 0; ks < 4; ks++) {
                const int gks = kc * 4 + ks;
                uint32_t a[4][4];
#pragma unroll
                for (int mt = 0; mt < 4; mt++) {
                    int r = wm * 64 + mt * 16 + (lane & 15);
                    uint32_t addr = Abase + r * 512
                                  + (((2 * gks + (lane >> 4)) ^ (r & 7)) * 16);
                    LDSM_X4(a[mt], addr);
                }
                uint32_t b[4][2];
#pragma unroll
                for (int nt = 0; nt < 4; nt++) {
                    int n = wn * 32 + nt * 8 + (lane & 7);
                    uint32_t addr = Bslot + n * 128
                                  + (((2 * ks + ((lane >> 3) & 1)) ^ (n & 7)) * 16);
                    LDSM_X2(b[nt], addr);
                }
#pragma unroll
                for (int mt = 0; mt < 4; mt++)
#pragma unroll
                    for (int nt = 0; nt < 4; nt++)
                        MMA16816(d[mt][nt], a[mt], b[nt]);
            }

            if (kc == 3) {                      // tile finished: fused epilogue
                const int tile = bid + (c >> 2) * NGRID;
                float* ah = acc + ((tile >= NTILES / 2) ? 256 : 0);
#pragma unroll
                for (int mt = 0; mt < 4; mt++) {
                    float slo = 0.0f, shi = 0.0f;
#pragma unroll
                    for (int nt = 0; nt < 4; nt++) {
                        slo += __expf(fmaf(d[mt][nt][0], TEMP_INV, -SHIFT))
                             + __expf(fmaf(d[mt][nt][1], TEMP_INV, -SHIFT));
                        shi += __expf(fmaf(d[mt][nt][2], TEMP_INV, -SHIFT))
                             + __expf(fmaf(d[mt][nt][3], TEMP_INV, -SHIFT));
#pragma unroll
                        for (int q = 0; q < 4; q++) d[mt][nt][q] = 0.0f;
                    }
#pragma unroll
                    for (int o = 1; o <= 2; o <<= 1) {
                        slo += __shfl_xor_sync(0xffffffffu, slo, o);
                        shi += __shfl_xor_sync(0xffffffffu, shi, o);
                    }
                    if ((lane & 3) == 0) {
                        int r = wm * 64 + mt * 16 + (lane >> 2);
                        atomicAdd(&ah[r], slo);
                        atomicAdd(&ah[r + 8], shi);
                    }
                }
            }
        }
    }

    // ---- flush + last-CTA fold ----
    __syncthreads();
    atomicAdd(&g_sums[t], acc[t]);
    __threadfence();

    __shared__ int lastflag;
    if (t == 0) lastflag = (atomicAdd(&g_done, 1) == NGRID - 1);
    __syncthreads();

    if (lastflag) {
        __shared__ float smm[8], smh[8];
        if (t < 256) {
            // __ldcg: L2-coherent reads of other CTAs' atomics / fenced stores
            float dm = (logf(__ldcg(&g_sums[t]))      + SHIFT) - __ldcg(&g_tgt[t]);
            float dh = (logf(__ldcg(&g_sums[BB + t])) + SHIFT) - __ldcg(&g_tgt[BB + t]);
#pragma unroll
            for (int o = 16; o > 0; o >>= 1) {
                dm += __shfl_xor_sync(0xffffffffu, dm, o);
                dh += __shfl_xor_sync(0xffffffffu, dh, o);
            }
            if ((t & 31) == 0) { smm[t >> 5] = dm; smh[t >> 5] = dh; }
        }
        __syncthreads();
        if (t == 0) {
            float sm = 0.0f, sh = 0.0f;
#pragma unroll
            for (int i = 0; i < 8; i++) { sm += smm[i]; sh += smh[i]; }
            out[0] = 0.5f * (sh * (1.0f / BB) + fmaxf(sm * (1.0f / BB) - RR, 0.0f));
        }
        // reset globals for next graph replay (invariant: zeroed after each run)
        __syncthreads();
        g_sums[t] = 0.0f;
        if (t == 0) g_done = 0;
    }
}

extern "C" void kernel_launch(void* const* d_in, const int* in_sizes, int n_in,
                              void* d_out, int out_size) {
    const float* inp     = (const float*)d_in[0];
    const void*  targets = d_in[1];
    const float* feat    = (const float*)d_in[2];
    float* out = (float*)d_out;

    cudaFuncSetAttribute(main_kernel, cudaFuncAttributeMaxDynamicSharedMemorySize, SM_TOTAL);
    main_kernel<<<NGRID, 512, SM_TOTAL>>>(inp, feat, targets, out);
}